// round 7
// baseline (speedup 1.0000x reference)
#include <cuda_runtime.h>
#include <cstdint>
#include <math.h>

#define BATCH 256
#define SEQ 256
#define IN_DIM 128
#define HID 1024
#define OUT_DIM 10
#define KTOT 1152            // [h | x_t] fused K
#define BK 32
#define BM 32
#define BN 64
#define PAD 4
#define LDW (BK + PAD)       // 36 floats row stride
#define NT 256               // 8 warps = 2/SMSP

// stage layout (bytes): Ah[32][36] Al[32][36] Bh[64][36] Bl[64][36]
#define OFF_AL 4608
#define OFF_BH 9216
#define OFF_BL 18432
#define STAGE_B 27648
#define NSTAGE 3
#define DYN_B (NSTAGE * STAGE_B)   // 82944

// ---- device-global scratch (sanctioned) ----
__device__ float g_hh[2][BATCH * HID];   // hidden hi split (ping-pong)
__device__ float g_hl[2][BATCH * HID];   // hidden lo split
__device__ float g_xh[BATCH * SEQ * IN_DIM];
__device__ float g_xl[BATCH * SEQ * IN_DIM];
__device__ float g_Wh[HID * KTOT];       // W^T [n][k] hi
__device__ float g_Wl[HID * KTOT];       // lo

__device__ __forceinline__ float tf32_rn(float f) {
    unsigned u;
    asm("cvt.rna.tf32.f32 %0, %1;" : "=r"(u) : "f"(f));
    return __uint_as_float(u);
}
__device__ __forceinline__ void cp16(void* smem_dst, const void* g) {
    unsigned d = (unsigned)__cvta_generic_to_shared(smem_dst);
    asm volatile("cp.async.ca.shared.global [%0], [%1], 16;\n" :: "r"(d), "l"(g));
}
__device__ __forceinline__ void cp_commit() { asm volatile("cp.async.commit_group;\n"); }
template <int N>
__device__ __forceinline__ void cp_wait() { asm volatile("cp.async.wait_group %0;\n" :: "n"(N)); }

__device__ __forceinline__ void mma_tf32(float* c, const unsigned* a, unsigned b0, unsigned b1) {
    asm volatile(
        "mma.sync.aligned.m16n8k8.row.col.f32.tf32.tf32.f32 "
        "{%0,%1,%2,%3}, {%4,%5,%6,%7}, {%8,%9}, {%0,%1,%2,%3};"
        : "+f"(c[0]), "+f"(c[1]), "+f"(c[2]), "+f"(c[3])
        : "r"(a[0]), "r"(a[1]), "r"(a[2]), "r"(a[3]), "r"(b0), "r"(b1));
}

// ---- prep: transpose+split W, split x ----
__global__ void split_w(const float* __restrict__ Whh, const float* __restrict__ Whx) {
    int k = blockIdx.x;                          // 0..1151
    for (int n = threadIdx.x; n < HID; n += blockDim.x) {
        float w = (k < HID) ? Whh[(long)k * HID + n] : Whx[(long)(k - HID) * HID + n];
        float hi = tf32_rn(w);
        g_Wh[(long)n * KTOT + k] = hi;
        g_Wl[(long)n * KTOT + k] = tf32_rn(w - hi);
    }
}
__global__ void split_x(const float* __restrict__ x) {
    long i = (long)blockIdx.x * blockDim.x + threadIdx.x;
    if (i < (long)BATCH * SEQ * IN_DIM) {
        float v = x[i];
        float hi = tf32_rn(v);
        g_xh[i] = hi;
        g_xl[i] = tf32_rn(v - hi);
    }
}

// ---- one recurrence step: 3xTF32 via mma.sync ----
// grid (16, 8) = 128 CTAs, 256 threads (8 warps), warp tile 16x16 (2m x 4n).
__global__ __launch_bounds__(NT, 1) void rnn_step(
    const float* __restrict__ bh, int t)
{
    extern __shared__ char smem[];

    const int tid  = threadIdx.x;
    const int wid  = tid >> 5;
    const int lane = tid & 31;
    const int g    = lane >> 2;     // fragment group 0..7
    const int tg   = lane & 3;      // thread-in-group 0..3
    const int wm   = wid & 1;       // warp m 0..1 (16 rows)
    const int wn   = wid >> 1;      // warp n 0..3 (16 cols)

    const int bm = blockIdx.y * BM;
    const int bn = blockIdx.x * BN;

    const float* hh_in = g_hh[t & 1];
    const float* hl_in = g_hl[t & 1];
    float* hh_out = g_hh[(t & 1) ^ 1];
    float* hl_out = g_hl[(t & 1) ^ 1];

    const int kstart = (t == 0) ? HID : 0;      // t==0: h0==0, only x chunks
    const int NC = (KTOT - kstart) / BK;

    auto load_chunk = [&](int ci, int s) {
        const int k0 = kstart + ci * BK;
        char* st = smem + s * STAGE_B;
        float* Ah = (float*)st;
        float* Al = (float*)(st + OFF_AL);
        float* Bh = (float*)(st + OFF_BH);
        float* Bl = (float*)(st + OFF_BL);
        const bool isH = (k0 < HID);
        {                                        // A: 32x32 = 256 float4 slots
            int m  = tid >> 3;
            int kq = (tid & 7) << 2;
            const float *sh, *sl;
            if (isH) {
                long o = (long)(bm + m) * HID + k0 + kq;
                sh = hh_in + o; sl = hl_in + o;
            } else {
                long o = (long)(bm + m) * (SEQ * IN_DIM) + (long)t * IN_DIM + (k0 - HID) + kq;
                sh = g_xh + o; sl = g_xl + o;
            }
            cp16(&Ah[m * LDW + kq], sh);
            cp16(&Al[m * LDW + kq], sl);
        }
        #pragma unroll
        for (int r = 0; r < 2; r++) {            // B: 64x32 = 512 float4 slots
            int idx = tid + r * NT;
            int n  = idx >> 3;
            int kq = (idx & 7) << 2;
            long o = (long)(bn + n) * KTOT + k0 + kq;
            cp16(&Bh[n * LDW + kq], g_Wh + o);
            cp16(&Bl[n * LDW + kq], g_Wl + o);
        }
        cp_commit();
    };

    float c[2][4] = {};                          // 2 n8-tiles x 4 regs

    load_chunk(0, 0);
    load_chunk(1, 1);   // NC >= 4 always

    for (int i = 0; i < NC; i++) {
        const int buf = i % NSTAGE;
        if (i + 2 < NC) {
            load_chunk(i + 2, (i + 2) % NSTAGE);
            cp_wait<2>();                        // chunk i complete; i+1,i+2 in flight
        } else if (i + 1 < NC) {
            cp_wait<1>();
        } else {
            cp_wait<0>();
        }
        __syncthreads();

        char* st = smem + buf * STAGE_B;
        const unsigned* Ah = (const unsigned*)st;
        const unsigned* Al = (const unsigned*)(st + OFF_AL);
        const unsigned* Bh = (const unsigned*)(st + OFF_BH);
        const unsigned* Bl = (const unsigned*)(st + OFF_BL);

        #pragma unroll
        for (int kb = 0; kb < BK; kb += 8) {
            const int ar0 = (wm * 16 + g) * LDW;
            const int ar1 = ar0 + 8 * LDW;
            unsigned ah[4], al[4];
            ah[0] = Ah[ar0 + kb + tg];     ah[1] = Ah[ar1 + kb + tg];
            ah[2] = Ah[ar0 + kb + tg + 4]; ah[3] = Ah[ar1 + kb + tg + 4];
            al[0] = Al[ar0 + kb + tg];     al[1] = Al[ar1 + kb + tg];
            al[2] = Al[ar0 + kb + tg + 4]; al[3] = Al[ar1 + kb + tg + 4];
            #pragma unroll
            for (int j = 0; j < 2; j++) {
                const int nr = (wn * 16 + j * 8 + g) * LDW;
                unsigned bh0 = Bh[nr + kb + tg], bh1 = Bh[nr + kb + tg + 4];
                unsigned bl0 = Bl[nr + kb + tg], bl1 = Bl[nr + kb + tg + 4];
                mma_tf32(c[j], ah, bh0, bh1);   // Ah*Bh
                mma_tf32(c[j], ah, bl0, bl1);   // Ah*Bl
                mma_tf32(c[j], al, bh0, bh1);   // Al*Bh
            }
        }
        __syncthreads();
    }

    // epilogue: bias + tanh + tf32 hi/lo split, direct from fragments
    #pragma unroll
    for (int j = 0; j < 2; j++) {
        #pragma unroll
        for (int rgi = 0; rgi < 4; rgi++) {
            int row = bm + wm * 16 + g + ((rgi >> 1) << 3);
            int col = bn + wn * 16 + j * 8 + tg * 2 + (rgi & 1);
            float h = tanhf(c[j][rgi] + __ldg(&bh[col]));
            float hi = tf32_rn(h);
            long o = (long)row * HID + col;
            hh_out[o] = hi;
            hl_out[o] = tf32_rn(h - hi);
        }
    }
}

// ---- final projection + softmax ----
__global__ __launch_bounds__(128) void rnn_out(
    const float* __restrict__ Why, const float* __restrict__ bo, float* __restrict__ out)
{
    const int b = blockIdx.x;
    const int tid = threadIdx.x;
    const float* hh = g_hh[0];   // t=255 writes buffer 0
    const float* hl = g_hl[0];

    float acc[OUT_DIM];
    #pragma unroll
    for (int o = 0; o < OUT_DIM; o++) acc[o] = 0.0f;

    for (int k = tid; k < HID; k += 128) {
        float hv = hh[(long)b * HID + k] + hl[(long)b * HID + k];
        #pragma unroll
        for (int o = 0; o < OUT_DIM; o++)
            acc[o] = fmaf(hv, Why[k * OUT_DIM + o], acc[o]);
    }

    __shared__ float red[128][OUT_DIM];
    #pragma unroll
    for (int o = 0; o < OUT_DIM; o++) red[tid][o] = acc[o];
    __syncthreads();
    for (int s = 64; s > 0; s >>= 1) {
        if (tid < s) {
            #pragma unroll
            for (int o = 0; o < OUT_DIM; o++) red[tid][o] += red[tid + s][o];
        }
        __syncthreads();
    }
    if (tid == 0) {
        float lg[OUT_DIM];
        float mx = -1e30f;
        #pragma unroll
        for (int o = 0; o < OUT_DIM; o++) { lg[o] = red[0][o] + bo[o]; mx = fmaxf(mx, lg[o]); }
        float ssum = 0.0f;
        #pragma unroll
        for (int o = 0; o < OUT_DIM; o++) { lg[o] = expf(lg[o] - mx); ssum += lg[o]; }
        float inv = 1.0f / ssum;
        #pragma unroll
        for (int o = 0; o < OUT_DIM; o++) out[(long)b * OUT_DIM + o] = lg[o] * inv;
    }
}

extern "C" void kernel_launch(void* const* d_in, const int* in_sizes, int n_in,
                              void* d_out, int out_size) {
    const float* x   = (const float*)d_in[0];
    const float* Whx = (const float*)d_in[1];
    const float* Whh = (const float*)d_in[2];
    const float* bh  = (const float*)d_in[3];
    const float* Why = (const float*)d_in[4];
    const float* bo  = (const float*)d_in[5];
    float* out = (float*)d_out;

    cudaFuncSetAttribute(rnn_step, cudaFuncAttributeMaxDynamicSharedMemorySize, DYN_B);

    split_w<<<KTOT, 256>>>(Whh, Whx);
    split_x<<<(BATCH * SEQ * IN_DIM) / 256, 256>>>(x);

    dim3 grid(HID / BN, BATCH / BM);   // (16, 8) = 128 CTAs
    for (int t = 0; t < SEQ; t++)
        rnn_step<<<grid, NT, DYN_B>>>(bh, t);
    rnn_out<<<BATCH, 128>>>(Why, bo, out);
}

// round 8
// speedup vs baseline: 1.0305x; 1.0305x over previous
#include <cuda_runtime.h>
#include <cstdint>
#include <math.h>

#define BATCH 256
#define SEQ 256
#define IN_DIM 128
#define HID 1024
#define OUT_DIM 10
#define KTOT 1152            // [h | x_t] fused K
#define BK 32
#define BM 32
#define BN 64
#define PAD 4
#define LDW (BK + PAD)       // 36 floats row stride
#define NT 256               // 8 warps = 2/SMSP

// stage layout (bytes): Ah[32][36] Al[32][36] Bh[64][36] Bl[64][36]
#define OFF_AL 4608
#define OFF_BH 9216
#define OFF_BL 18432
#define STAGE_B 27648
#define NSTAGE 3
#define DYN_B (NSTAGE * STAGE_B)   // 82944

// ---- device-global scratch (sanctioned) ----
__device__ float g_hh[2][BATCH * HID];   // hidden hi split (ping-pong)
__device__ float g_hl[2][BATCH * HID];   // hidden lo split
__device__ float g_xh[BATCH * SEQ * IN_DIM];
__device__ float g_xl[BATCH * SEQ * IN_DIM];
__device__ float g_Wh[HID * KTOT];       // W^T [n][k] hi
__device__ float g_Wl[HID * KTOT];       // lo

__device__ __forceinline__ float tf32_rn(float f) {
    unsigned u;
    asm("cvt.rna.tf32.f32 %0, %1;" : "=r"(u) : "f"(f));
    return __uint_as_float(u);
}
__device__ __forceinline__ void cp16(void* smem_dst, const void* g) {
    unsigned d = (unsigned)__cvta_generic_to_shared(smem_dst);
    asm volatile("cp.async.ca.shared.global [%0], [%1], 16;\n" :: "r"(d), "l"(g));
}
__device__ __forceinline__ void cp_commit() { asm volatile("cp.async.commit_group;\n"); }
template <int N>
__device__ __forceinline__ void cp_wait() { asm volatile("cp.async.wait_group %0;\n" :: "n"(N)); }

__device__ __forceinline__ void ldsm4(unsigned* r, unsigned saddr) {
    asm volatile("ldmatrix.sync.aligned.m8n8.x4.shared.b16 {%0,%1,%2,%3}, [%4];"
                 : "=r"(r[0]), "=r"(r[1]), "=r"(r[2]), "=r"(r[3]) : "r"(saddr));
}
__device__ __forceinline__ void mma_tf32(float* c, const unsigned* a, unsigned b0, unsigned b1) {
    asm volatile(
        "mma.sync.aligned.m16n8k8.row.col.f32.tf32.tf32.f32 "
        "{%0,%1,%2,%3}, {%4,%5,%6,%7}, {%8,%9}, {%0,%1,%2,%3};"
        : "+f"(c[0]), "+f"(c[1]), "+f"(c[2]), "+f"(c[3])
        : "r"(a[0]), "r"(a[1]), "r"(a[2]), "r"(a[3]), "r"(b0), "r"(b1));
}

// ---- prep: transpose+split W, split x ----
__global__ void split_w(const float* __restrict__ Whh, const float* __restrict__ Whx) {
    int k = blockIdx.x;                          // 0..1151
    for (int n = threadIdx.x; n < HID; n += blockDim.x) {
        float w = (k < HID) ? Whh[(long)k * HID + n] : Whx[(long)(k - HID) * HID + n];
        float hi = tf32_rn(w);
        g_Wh[(long)n * KTOT + k] = hi;
        g_Wl[(long)n * KTOT + k] = tf32_rn(w - hi);
    }
}
__global__ void split_x(const float* __restrict__ x) {
    long i = (long)blockIdx.x * blockDim.x + threadIdx.x;
    if (i < (long)BATCH * SEQ * IN_DIM) {
        float v = x[i];
        float hi = tf32_rn(v);
        g_xh[i] = hi;
        g_xl[i] = tf32_rn(v - hi);
    }
}

// ---- one recurrence step: 3xTF32 via mma.sync + ldmatrix ----
// grid (16, 8) = 128 CTAs, 256 threads (8 warps), warp tile 16x16 (2m x 4n).
__global__ __launch_bounds__(NT, 1) void rnn_step(
    const float* __restrict__ bh, int t)
{
    extern __shared__ char smem[];

    const int tid  = threadIdx.x;
    const int wid  = tid >> 5;
    const int lane = tid & 31;
    const int g    = lane >> 2;     // fragment group 0..7
    const int tg   = lane & 3;      // thread-in-group 0..3
    const int wm   = wid & 1;       // warp m 0..1 (16 rows)
    const int wn   = wid >> 1;      // warp n 0..3 (16 cols)

    const int bm = blockIdx.y * BM;
    const int bn = blockIdx.x * BN;

    const unsigned sbase = (unsigned)__cvta_generic_to_shared(smem);

    // ldmatrix per-lane source offsets (bytes within a stage)
    // A (m16 x k8 tf32): mats [rows0-7,k0-3][rows8-15,k0-3][rows0-7,k4-7][rows8-15,k4-7]
    const int a_row = wm * 16 + (lane & 15);
    const int a_k4  = (lane >> 4) << 2;
    const unsigned aoff = (unsigned)(a_row * LDW + a_k4) * 4u;
    // B (n16 x k8): mats [n0-7,k0-3][n0-7,k4-7][n8-15,k0-3][n8-15,k4-7]
    const int b_row = wn * 16 + (lane & 7) + ((lane >> 4) << 3);
    const int b_k4  = ((lane >> 3) & 1) << 2;
    const unsigned boff = (unsigned)(b_row * LDW + b_k4) * 4u;

    const float* hh_in = g_hh[t & 1];
    const float* hl_in = g_hl[t & 1];
    float* hh_out = g_hh[(t & 1) ^ 1];
    float* hl_out = g_hl[(t & 1) ^ 1];

    const int kstart = (t == 0) ? HID : 0;      // t==0: h0==0, only x chunks
    const int NC = (KTOT - kstart) / BK;

    auto load_chunk = [&](int ci, int s) {
        const int k0 = kstart + ci * BK;
        char* st = smem + s * STAGE_B;
        float* Ah = (float*)st;
        float* Al = (float*)(st + OFF_AL);
        float* Bh = (float*)(st + OFF_BH);
        float* Bl = (float*)(st + OFF_BL);
        const bool isH = (k0 < HID);
        {                                        // A: 32x32 = 256 float4 slots
            int m  = tid >> 3;
            int kq = (tid & 7) << 2;
            const float *sh, *sl;
            if (isH) {
                long o = (long)(bm + m) * HID + k0 + kq;
                sh = hh_in + o; sl = hl_in + o;
            } else {
                long o = (long)(bm + m) * (SEQ * IN_DIM) + (long)t * IN_DIM + (k0 - HID) + kq;
                sh = g_xh + o; sl = g_xl + o;
            }
            cp16(&Ah[m * LDW + kq], sh);
            cp16(&Al[m * LDW + kq], sl);
        }
        #pragma unroll
        for (int r = 0; r < 2; r++) {            // B: 64x32 = 512 float4 slots
            int idx = tid + r * NT;
            int n  = idx >> 3;
            int kq = (idx & 7) << 2;
            long o = (long)(bn + n) * KTOT + k0 + kq;
            cp16(&Bh[n * LDW + kq], g_Wh + o);
            cp16(&Bl[n * LDW + kq], g_Wl + o);
        }
        cp_commit();
    };

    float c[2][4] = {};                          // 2 n8-tiles x 4 regs

    load_chunk(0, 0);
    load_chunk(1, 1);   // NC >= 4 always

    for (int i = 0; i < NC; i++) {
        const int buf = i % NSTAGE;
        if (i + 1 < NC) cp_wait<1>();            // chunk i landed (i+1 may be in flight)
        else            cp_wait<0>();
        __syncthreads();                         // single barrier per chunk:
                                                 // also fences reuse of buf (i+2)%3,
                                                 // last read in iter i-1 (pre-barrier)
        if (i + 2 < NC) load_chunk(i + 2, (i + 2) % NSTAGE);

        const unsigned sb = sbase + (unsigned)(buf * STAGE_B);
        #pragma unroll
        for (int kb = 0; kb < BK; kb += 8) {
            unsigned ah[4], al[4], bhf[4], blf[4];
            ldsm4(ah,  sb + aoff + kb * 4);
            ldsm4(al,  sb + OFF_AL + aoff + kb * 4);
            ldsm4(bhf, sb + OFF_BH + boff + kb * 4);
            ldsm4(blf, sb + OFF_BL + boff + kb * 4);
            #pragma unroll
            for (int j = 0; j < 2; j++) {
                mma_tf32(c[j], ah, bhf[2 * j], bhf[2 * j + 1]);   // Ah*Bh
                mma_tf32(c[j], ah, blf[2 * j], blf[2 * j + 1]);   // Ah*Bl
                mma_tf32(c[j], al, bhf[2 * j], bhf[2 * j + 1]);   // Al*Bh
            }
        }
    }

    // epilogue: bias + tanh + tf32 hi/lo split, direct from fragments
    #pragma unroll
    for (int j = 0; j < 2; j++) {
        #pragma unroll
        for (int rgi = 0; rgi < 4; rgi++) {
            int row = bm + wm * 16 + g + ((rgi >> 1) << 3);
            int col = bn + wn * 16 + j * 8 + tg * 2 + (rgi & 1);
            float h = tanhf(c[j][rgi] + __ldg(&bh[col]));
            float hi = tf32_rn(h);
            long o = (long)row * HID + col;
            hh_out[o] = hi;
            hl_out[o] = tf32_rn(h - hi);
        }
    }
}

// ---- final projection + softmax ----
__global__ __launch_bounds__(128) void rnn_out(
    const float* __restrict__ Why, const float* __restrict__ bo, float* __restrict__ out)
{
    const int b = blockIdx.x;
    const int tid = threadIdx.x;
    const float* hh = g_hh[0];   // t=255 writes buffer 0
    const float* hl = g_hl[0];

    float acc[OUT_DIM];
    #pragma unroll
    for (int o = 0; o < OUT_DIM; o++) acc[o] = 0.0f;

    for (int k = tid; k < HID; k += 128) {
        float hv = hh[(long)b * HID + k] + hl[(long)b * HID + k];
        #pragma unroll
        for (int o = 0; o < OUT_DIM; o++)
            acc[o] = fmaf(hv, Why[k * OUT_DIM + o], acc[o]);
    }

    __shared__ float red[128][OUT_DIM];
    #pragma unroll
    for (int o = 0; o < OUT_DIM; o++) red[tid][o] = acc[o];
    __syncthreads();
    for (int s = 64; s > 0; s >>= 1) {
        if (tid < s) {
            #pragma unroll
            for (int o = 0; o < OUT_DIM; o++) red[tid][o] += red[tid + s][o];
        }
        __syncthreads();
    }
    if (tid == 0) {
        float lg[OUT_DIM];
        float mx = -1e30f;
        #pragma unroll
        for (int o = 0; o < OUT_DIM; o++) { lg[o] = red[0][o] + bo[o]; mx = fmaxf(mx, lg[o]); }
        float ssum = 0.0f;
        #pragma unroll
        for (int o = 0; o < OUT_DIM; o++) { lg[o] = expf(lg[o] - mx); ssum += lg[o]; }
        float inv = 1.0f / ssum;
        #pragma unroll
        for (int o = 0; o < OUT_DIM; o++) out[(long)b * OUT_DIM + o] = lg[o] * inv;
    }
}

extern "C" void kernel_launch(void* const* d_in, const int* in_sizes, int n_in,
                              void* d_out, int out_size) {
    const float* x   = (const float*)d_in[0];
    const float* Whx = (const float*)d_in[1];
    const float* Whh = (const float*)d_in[2];
    const float* bh  = (const float*)d_in[3];
    const float* Why = (const float*)d_in[4];
    const float* bo  = (const float*)d_in[5];
    float* out = (float*)d_out;

    cudaFuncSetAttribute(rnn_step, cudaFuncAttributeMaxDynamicSharedMemorySize, DYN_B);

    split_w<<<KTOT, 256>>>(Whh, Whx);
    split_x<<<(BATCH * SEQ * IN_DIM) / 256, 256>>>(x);

    dim3 grid(HID / BN, BATCH / BM);   // (16, 8) = 128 CTAs
    for (int t = 0; t < SEQ; t++)
        rnn_step<<<grid, NT, DYN_B>>>(bh, t);
    rnn_out<<<BATCH, 128>>>(Why, bo, out);
}